// round 11
// baseline (speedup 1.0000x reference)
#include <cuda_runtime.h>

#define B_SZ   4
#define N_SZ   1024
#define DIN    128
#define DOUT   64
#define ITILE  8
#define JCHUNK 128
#define PAD    129
#define NTILES (B_SZ * N_SZ / ITILE)     // 512 i-tiles
#define SPLIT  4
#define CHUNKS_PER 2
#define PROWS  8                         // proj rows per block (grid = 512)

__device__ float g_x1[B_SZ * N_SZ * DOUT];
__device__ float g_x2[B_SZ * N_SZ * DOUT];
__device__ float g_c1[B_SZ * N_SZ];
__device__ float g_c2[B_SZ * N_SZ];
__device__ float g_acc[SPLIT * NTILES * ITILE * DIN];   // 8 MB
__device__ float g_rs [SPLIT * NTILES * ITILE];

__device__ __forceinline__ float lrelu(float v) { return fmaxf(v, 0.01f * v); }

typedef unsigned long long u64;

__device__ __forceinline__ u64 pk2(float v) {
    u64 r; unsigned u = __float_as_uint(v);
    asm("mov.b64 %0, {%1, %1};" : "=l"(r) : "r"(u)); return r;
}
__device__ __forceinline__ u64 add2(u64 a, u64 b) {
    u64 r; asm("add.rn.f32x2 %0, %1, %2;" : "=l"(r) : "l"(a), "l"(b)); return r;
}
__device__ __forceinline__ u64 fma2(u64 a, u64 b, u64 c) {
    u64 r; asm("fma.rn.f32x2 %0, %1, %2, %3;" : "=l"(r) : "l"(a), "l"(b), "l"(c)); return r;
}
__device__ __forceinline__ void upk(u64 v, float& lo, float& hi) {
    unsigned a, b; asm("mov.b64 {%0, %1}, %2;" : "=r"(a), "=r"(b) : "l"(v));
    lo = __uint_as_float(a); hi = __uint_as_float(b);
}
#define ABS2 0x7FFFFFFF7FFFFFFFULL

// ---------------------------------------------------------------------------
// Kernel 1: x1 = x@w1, x2 = x@w2, c1 = x1.a, c2 = x2.a
// 8 rows/block, 512 blocks, 256 threads: thread = (col k, row-pair rg).
// ---------------------------------------------------------------------------
__global__ void __launch_bounds__(256) proj_kernel(
    const float* __restrict__ x,
    const float* __restrict__ w1,
    const float* __restrict__ w2,
    const float* __restrict__ a)
{
    __shared__ float xs[PROWS][DIN];            // 4 KB
    __shared__ float cred[2][4][2][2];          // [mat][rg][warp-half][q]

    const int t    = threadIdx.x;
    const int k    = t & 63;                    // output col
    const int rg   = t >> 6;                    // row pair 0..3
    const int base = blockIdx.x * PROWS;

    // stage 8 x-rows: 256 float4, one per thread
    ((float4*)xs)[t] = ((const float4*)(x + (size_t)base * DIN))[t];
    __syncthreads();

    float a10 = 0.f, a11 = 0.f, a20 = 0.f, a21 = 0.f;
#pragma unroll 16
    for (int d = 0; d < DIN; ++d) {
        const float wv1 = w1[d * DOUT + k];     // coalesced, L2-resident
        const float wv2 = w2[d * DOUT + k];
        const float x0  = xs[rg * 2][d];        // warp-broadcast LDS
        const float x1v = xs[rg * 2 + 1][d];
        a10 += x0  * wv1;  a11 += x1v * wv1;
        a20 += x0  * wv2;  a21 += x1v * wv2;
    }

    const int row0 = base + rg * 2;
    g_x1[(size_t)row0 * DOUT + k]       = a10;
    g_x1[(size_t)(row0 + 1) * DOUT + k] = a11;
    g_x2[(size_t)row0 * DOUT + k]       = a20;
    g_x2[(size_t)(row0 + 1) * DOUT + k] = a21;

    // c1/c2 reduction over k (64 cols = 2 warps per rg)
    const float av = a[k];
    float p10 = a10 * av, p11 = a11 * av, p20 = a20 * av, p21 = a21 * av;
#pragma unroll
    for (int off = 16; off > 0; off >>= 1) {
        p10 += __shfl_xor_sync(0xFFFFFFFFu, p10, off);
        p11 += __shfl_xor_sync(0xFFFFFFFFu, p11, off);
        p20 += __shfl_xor_sync(0xFFFFFFFFu, p20, off);
        p21 += __shfl_xor_sync(0xFFFFFFFFu, p21, off);
    }
    const int half = (t >> 5) & 1;
    if ((t & 31) == 0) {
        cred[0][rg][half][0] = p10;  cred[0][rg][half][1] = p11;
        cred[1][rg][half][0] = p20;  cred[1][rg][half][1] = p21;
    }
    __syncthreads();
    if (t < PROWS) {
        const int g = t >> 1, q = t & 1;
        g_c1[base + t] = cred[0][g][0][q] + cred[0][g][1][q];
        g_c2[base + t] = cred[1][g][0][q] + cred[1][g][1][q];
    }
}

// ---------------------------------------------------------------------------
// Kernel 2: score + exp/mask + partial aggregation over a quarter j-range.
// ---------------------------------------------------------------------------
__global__ void __launch_bounds__(128, 6) gat_score_agg_kernel(
    const float* __restrict__ x,       // [B,N,DIN]
    const float* __restrict__ mask,    // [B,N,N]
    const float* __restrict__ a)       // [DOUT]
{
    __shared__ __align__(16) float pool[DOUT * PAD];   // x2s [d][j]; ws aliased
    __shared__ __align__(16) float x1f[DOUT * ITILE];  // [d][r]
    __shared__ __align__(16) u64   a2s[DOUT];
    __shared__ float c1s[ITILE];
    __shared__ float redm[ITILE][4];

    u64* const ws2 = (u64*)pool;

    const int t    = threadIdx.x;
    const int bi   = blockIdx.x;
    const int tile = bi >> 2;
    const int part = bi & 3;
    const int b    = tile >> 7;
    const int i0   = (tile & 127) * ITILE;

    for (int l = t; l < ITILE * DOUT; l += 128) {
        const int r = l >> 6, d = l & 63;
        x1f[d * ITILE + r] = g_x1[(b * N_SZ + i0 + r) * DOUT + d];
    }
    if (t < DOUT) a2s[t] = pk2(a[t]);
    if (t < ITILE) c1s[t] = 0.505f * g_c1[b * N_SZ + i0 + t];

    u64 acc[4]; float rs[ITILE];
#pragma unroll
    for (int p = 0; p < 4; ++p) acc[p] = 0ULL;
#pragma unroll
    for (int r = 0; r < ITILE; ++r) rs[r] = 0.f;

    for (int c = 0; c < CHUNKS_PER; ++c) {
        const int jc = part * CHUNKS_PER + c;

        const float4* x2g4 = (const float4*)(g_x2 + (b * N_SZ + jc * JCHUNK) * DOUT);
        for (int l = t; l < JCHUNK * DOUT / 4; l += 128) {
            const float4 v = x2g4[l];
            const int j = l >> 4;
            const int d = (l & 15) * 4;
            pool[(d + 0) * PAD + j] = v.x;
            pool[(d + 1) * PAD + j] = v.y;
            pool[(d + 2) * PAD + j] = v.z;
            pool[(d + 3) * PAD + j] = v.w;
        }
        __syncthreads();                                   // x2s staged

        u64 T[4];
#pragma unroll
        for (int p = 0; p < 4; ++p) T[p] = 0ULL;

#pragma unroll 16
        for (int d = 0; d < DOUT; ++d) {
            const u64 xv2 = pk2(pool[d * PAD + t]);
            const u64 ad2 = a2s[d];
            const ulonglong2 xa = ((const ulonglong2*)x1f)[d * 2];
            const ulonglong2 xb = ((const ulonglong2*)x1f)[d * 2 + 1];
            T[0] = fma2(add2(xa.x, xv2) & ABS2, ad2, T[0]);
            T[1] = fma2(add2(xa.y, xv2) & ABS2, ad2, T[1]);
            T[2] = fma2(add2(xb.x, xv2) & ABS2, ad2, T[2]);
            T[3] = fma2(add2(xb.y, xv2) & ABS2, ad2, T[3]);
        }
        __syncthreads();                                   // x2s reads done (ws alias)

        const int j = jc * JCHUNK + t;
        const float c2j = 0.505f * g_c2[b * N_SZ + j];
        const float* mrow = mask + ((size_t)b * N_SZ + i0) * N_SZ + j;
        float w[ITILE];
#pragma unroll
        for (int p = 0; p < 4; ++p) {
            float t0, t1; upk(T[p], t0, t1);
            const float S0 = fmaf(0.495f, t0, c1s[2 * p]     + c2j);
            const float S1 = fmaf(0.495f, t1, c1s[2 * p + 1] + c2j);
            const float th0 = 1.0f - __fdividef(2.0f, __expf(S0 * 0.25f) + 1.0f);
            const float th1 = 1.0f - __fdividef(2.0f, __expf(S1 * 0.25f) + 1.0f);
            w[2 * p]     = __expf(8.0f * th0) * mrow[(size_t)(2 * p)     * N_SZ];
            w[2 * p + 1] = __expf(8.0f * th1) * mrow[(size_t)(2 * p + 1) * N_SZ];
            rs[2 * p]     += w[2 * p];
            rs[2 * p + 1] += w[2 * p + 1];
        }
        ((float4*)ws2)[t * 2]     = make_float4(w[0], w[1], w[2], w[3]);
        ((float4*)ws2)[t * 2 + 1] = make_float4(w[4], w[5], w[6], w[7]);
        __syncthreads();                                   // ws visible

        const float* xg = x + ((size_t)b * N_SZ + jc * JCHUNK) * DIN + t;
#pragma unroll 4
        for (int jj = 0; jj < JCHUNK; ++jj) {
            const ulonglong2 wA = ((const ulonglong2*)ws2)[jj * 2];
            const ulonglong2 wB = ((const ulonglong2*)ws2)[jj * 2 + 1];
            const u64 xv2 = pk2(xg[(size_t)jj * DIN]);
            acc[0] = fma2(wA.x, xv2, acc[0]);
            acc[1] = fma2(wA.y, xv2, acc[1]);
            acc[2] = fma2(wB.x, xv2, acc[2]);
            acc[3] = fma2(wB.y, xv2, acc[3]);
        }
        __syncthreads();                                   // agg done before restage
    }

#pragma unroll
    for (int off = 16; off > 0; off >>= 1)
#pragma unroll
        for (int r = 0; r < ITILE; ++r)
            rs[r] += __shfl_xor_sync(0xFFFFFFFFu, rs[r], off);
    const int warp = t >> 5, lane = t & 31;
    if (lane == 0)
#pragma unroll
        for (int r = 0; r < ITILE; ++r) redm[r][warp] = rs[r];

    float* ap = g_acc + (size_t)bi * ITILE * DIN + t;
#pragma unroll
    for (int p = 0; p < 4; ++p) {
        float lo, hi; upk(acc[p], lo, hi);
        ap[(2 * p) * DIN]     = lo;
        ap[(2 * p + 1) * DIN] = hi;
    }
    __syncthreads();
    if (t < ITILE)
        g_rs[bi * ITILE + t] = redm[t][0] + redm[t][1] + redm[t][2] + redm[t][3];
}

// ---------------------------------------------------------------------------
// Kernel 3: combine 4 partials + linear + lrelu. 256 threads, 2 outputs each.
// ---------------------------------------------------------------------------
__global__ void __launch_bounds__(256) gat_epilogue_kernel(
    const float* __restrict__ lin_w,   // [DOUT,DIN]
    float* __restrict__ out)           // [B,N,DOUT]
{
    __shared__ float outv[ITILE][DIN];
    __shared__ float red[ITILE];

    const int t    = threadIdx.x;
    const int tile = blockIdx.x;
    const int b    = tile >> 7;
    const int i0   = (tile & 127) * ITILE;

    const float* base = g_acc + (size_t)tile * SPLIT * ITILE * DIN;
    for (int l = t; l < ITILE * DIN; l += 256) {
        float s = base[l];
#pragma unroll
        for (int p = 1; p < SPLIT; ++p) s += base[p * ITILE * DIN + l];
        ((float*)outv)[l] = s;
    }
    if (t < ITILE) {
        float s = 0.f;
#pragma unroll
        for (int p = 0; p < SPLIT; ++p) s += g_rs[(tile * SPLIT + p) * ITILE + t];
        red[t] = s;
    }
    __syncthreads();

    const int k  = t & 63;
    const int rg = t >> 6;
    const float* lw = lin_w + k * DIN;
    float y0 = 0.f, y1 = 0.f;
#pragma unroll 8
    for (int d = 0; d < DIN; d += 4) {
        const float4 l4 = *(const float4*)&lw[d];
        const float4 oa = *(const float4*)&outv[rg][d];
        const float4 ob = *(const float4*)&outv[rg + 4][d];
        y0 += oa.x * l4.x + oa.y * l4.y + oa.z * l4.z + oa.w * l4.w;
        y1 += ob.x * l4.x + ob.y * l4.y + ob.z * l4.z + ob.w * l4.w;
    }
    const float inv0 = 1.0f / red[rg];
    const float inv1 = 1.0f / red[rg + 4];
    out[((size_t)b * N_SZ + i0 + rg)     * DOUT + k] = lrelu(y0) * inv0;
    out[((size_t)b * N_SZ + i0 + rg + 4) * DOUT + k] = lrelu(y1) * inv1;
}

// ---------------------------------------------------------------------------
extern "C" void kernel_launch(void* const* d_in, const int* in_sizes, int n_in,
                              void* d_out, int out_size)
{
    const float* x     = (const float*)d_in[0];
    const float* A_shp = (const float*)d_in[1];
    const float* w1    = (const float*)d_in[2];
    const float* w2    = (const float*)d_in[3];
    const float* a     = (const float*)d_in[4];
    const float* lin_w = (const float*)d_in[5];
    float* out = (float*)d_out;

    proj_kernel<<<B_SZ * N_SZ / PROWS, 256>>>(x, w1, w2, a);
    gat_score_agg_kernel<<<SPLIT * NTILES, 128>>>(x, A_shp, a);
    gat_epilogue_kernel<<<NTILES, 256>>>(lin_w, out);
}

// round 12
// speedup vs baseline: 1.5904x; 1.5904x over previous
#include <cuda_runtime.h>

#define B_SZ   4
#define N_SZ   1024
#define DIN    128
#define DOUT   64
#define ITILE  8
#define JCHUNK 128
#define PAD    129
#define NTILES (B_SZ * N_SZ / ITILE)     // 512 i-tiles
#define SPLIT  4
#define CHUNKS_PER 2
#define PROWS  8                         // proj rows per block (grid = 512)

__device__ float g_x1[B_SZ * N_SZ * DOUT];
__device__ float g_x2[B_SZ * N_SZ * DOUT];
__device__ float g_c1[B_SZ * N_SZ];
__device__ float g_c2[B_SZ * N_SZ];
__device__ float g_acc[SPLIT * NTILES * ITILE * DIN];   // 8 MB
__device__ float g_rs [SPLIT * NTILES * ITILE];

__device__ __forceinline__ float lrelu(float v) { return fmaxf(v, 0.01f * v); }

typedef unsigned long long u64;

__device__ __forceinline__ u64 pk2(float v) {
    u64 r; unsigned u = __float_as_uint(v);
    asm("mov.b64 %0, {%1, %1};" : "=l"(r) : "r"(u)); return r;
}
__device__ __forceinline__ u64 add2(u64 a, u64 b) {
    u64 r; asm("add.rn.f32x2 %0, %1, %2;" : "=l"(r) : "l"(a), "l"(b)); return r;
}
__device__ __forceinline__ u64 fma2(u64 a, u64 b, u64 c) {
    u64 r; asm("fma.rn.f32x2 %0, %1, %2, %3;" : "=l"(r) : "l"(a), "l"(b), "l"(c)); return r;
}
__device__ __forceinline__ void upk(u64 v, float& lo, float& hi) {
    unsigned a, b; asm("mov.b64 {%0, %1}, %2;" : "=r"(a), "=r"(b) : "l"(v));
    lo = __uint_as_float(a); hi = __uint_as_float(b);
}
#define ABS2 0x7FFFFFFF7FFFFFFFULL

// ---------------------------------------------------------------------------
// Kernel 1: x1 = x@w1, x2 = x@w2, c1 = x1.a, c2 = x2.a
// 8 rows/block, 512 blocks, 256 threads: thread = (col k, row-pair rg).
// ---------------------------------------------------------------------------
__global__ void __launch_bounds__(256) proj_kernel(
    const float* __restrict__ x,
    const float* __restrict__ w1,
    const float* __restrict__ w2,
    const float* __restrict__ a)
{
    __shared__ float xs[PROWS][DIN];            // 4 KB
    __shared__ float cred[2][4][2][2];          // [mat][rg][warp-half][q]

    const int t    = threadIdx.x;
    const int k    = t & 63;                    // output col
    const int rg   = t >> 6;                    // row pair 0..3
    const int base = blockIdx.x * PROWS;

    // stage 8 x-rows: 256 float4, one per thread
    ((float4*)xs)[t] = ((const float4*)(x + (size_t)base * DIN))[t];
    __syncthreads();

    float a10 = 0.f, a11 = 0.f, a20 = 0.f, a21 = 0.f;
#pragma unroll 16
    for (int d = 0; d < DIN; ++d) {
        const float wv1 = w1[d * DOUT + k];     // coalesced, L2-resident
        const float wv2 = w2[d * DOUT + k];
        const float x0  = xs[rg * 2][d];        // warp-broadcast LDS
        const float x1v = xs[rg * 2 + 1][d];
        a10 += x0  * wv1;  a11 += x1v * wv1;
        a20 += x0  * wv2;  a21 += x1v * wv2;
    }

    const int row0 = base + rg * 2;
    g_x1[(size_t)row0 * DOUT + k]       = a10;
    g_x1[(size_t)(row0 + 1) * DOUT + k] = a11;
    g_x2[(size_t)row0 * DOUT + k]       = a20;
    g_x2[(size_t)(row0 + 1) * DOUT + k] = a21;

    // c1/c2 reduction over k (64 cols = 2 warps per rg)
    const float av = a[k];
    float p10 = a10 * av, p11 = a11 * av, p20 = a20 * av, p21 = a21 * av;
#pragma unroll
    for (int off = 16; off > 0; off >>= 1) {
        p10 += __shfl_xor_sync(0xFFFFFFFFu, p10, off);
        p11 += __shfl_xor_sync(0xFFFFFFFFu, p11, off);
        p20 += __shfl_xor_sync(0xFFFFFFFFu, p20, off);
        p21 += __shfl_xor_sync(0xFFFFFFFFu, p21, off);
    }
    const int half = (t >> 5) & 1;
    if ((t & 31) == 0) {
        cred[0][rg][half][0] = p10;  cred[0][rg][half][1] = p11;
        cred[1][rg][half][0] = p20;  cred[1][rg][half][1] = p21;
    }
    __syncthreads();
    if (t < PROWS) {
        const int g = t >> 1, q = t & 1;
        g_c1[base + t] = cred[0][g][0][q] + cred[0][g][1][q];
        g_c2[base + t] = cred[1][g][0][q] + cred[1][g][1][q];
    }
}

// ---------------------------------------------------------------------------
// Kernel 2: score + exp/mask + partial aggregation over a quarter j-range.
// ---------------------------------------------------------------------------
__global__ void __launch_bounds__(128, 6) gat_score_agg_kernel(
    const float* __restrict__ x,       // [B,N,DIN]
    const float* __restrict__ mask,    // [B,N,N]
    const float* __restrict__ a)       // [DOUT]
{
    __shared__ __align__(16) float pool[DOUT * PAD];   // x2s [d][j]; ws aliased
    __shared__ __align__(16) float x1f[DOUT * ITILE];  // [d][r]
    __shared__ __align__(16) u64   a2s[DOUT];
    __shared__ float c1s[ITILE];
    __shared__ float redm[ITILE][4];

    u64* const ws2 = (u64*)pool;

    const int t    = threadIdx.x;
    const int bi   = blockIdx.x;
    const int tile = bi >> 2;
    const int part = bi & 3;
    const int b    = tile >> 7;
    const int i0   = (tile & 127) * ITILE;

    for (int l = t; l < ITILE * DOUT; l += 128) {
        const int r = l >> 6, d = l & 63;
        x1f[d * ITILE + r] = g_x1[(b * N_SZ + i0 + r) * DOUT + d];
    }
    if (t < DOUT) a2s[t] = pk2(a[t]);
    if (t < ITILE) c1s[t] = 0.505f * g_c1[b * N_SZ + i0 + t];

    u64 acc[4]; float rs[ITILE];
#pragma unroll
    for (int p = 0; p < 4; ++p) acc[p] = 0ULL;
#pragma unroll
    for (int r = 0; r < ITILE; ++r) rs[r] = 0.f;

    for (int c = 0; c < CHUNKS_PER; ++c) {
        const int jc = part * CHUNKS_PER + c;

        const float4* x2g4 = (const float4*)(g_x2 + (b * N_SZ + jc * JCHUNK) * DOUT);
        for (int l = t; l < JCHUNK * DOUT / 4; l += 128) {
            const float4 v = x2g4[l];
            const int j = l >> 4;
            const int d = (l & 15) * 4;
            pool[(d + 0) * PAD + j] = v.x;
            pool[(d + 1) * PAD + j] = v.y;
            pool[(d + 2) * PAD + j] = v.z;
            pool[(d + 3) * PAD + j] = v.w;
        }
        __syncthreads();                                   // x2s staged

        u64 T[4];
#pragma unroll
        for (int p = 0; p < 4; ++p) T[p] = 0ULL;

#pragma unroll 16
        for (int d = 0; d < DOUT; ++d) {
            const u64 xv2 = pk2(pool[d * PAD + t]);
            const u64 ad2 = a2s[d];
            const ulonglong2 xa = ((const ulonglong2*)x1f)[d * 2];
            const ulonglong2 xb = ((const ulonglong2*)x1f)[d * 2 + 1];
            T[0] = fma2(add2(xa.x, xv2) & ABS2, ad2, T[0]);
            T[1] = fma2(add2(xa.y, xv2) & ABS2, ad2, T[1]);
            T[2] = fma2(add2(xb.x, xv2) & ABS2, ad2, T[2]);
            T[3] = fma2(add2(xb.y, xv2) & ABS2, ad2, T[3]);
        }
        __syncthreads();                                   // x2s reads done (ws alias)

        const int j = jc * JCHUNK + t;
        const float c2j = 0.505f * g_c2[b * N_SZ + j];
        const float* mrow = mask + ((size_t)b * N_SZ + i0) * N_SZ + j;
        float w[ITILE];
#pragma unroll
        for (int p = 0; p < 4; ++p) {
            float t0, t1; upk(T[p], t0, t1);
            const float S0 = fmaf(0.495f, t0, c1s[2 * p]     + c2j);
            const float S1 = fmaf(0.495f, t1, c1s[2 * p + 1] + c2j);
            const float th0 = 1.0f - __fdividef(2.0f, __expf(S0 * 0.25f) + 1.0f);
            const float th1 = 1.0f - __fdividef(2.0f, __expf(S1 * 0.25f) + 1.0f);
            w[2 * p]     = __expf(8.0f * th0) * mrow[(size_t)(2 * p)     * N_SZ];
            w[2 * p + 1] = __expf(8.0f * th1) * mrow[(size_t)(2 * p + 1) * N_SZ];
            rs[2 * p]     += w[2 * p];
            rs[2 * p + 1] += w[2 * p + 1];
        }
        ((float4*)ws2)[t * 2]     = make_float4(w[0], w[1], w[2], w[3]);
        ((float4*)ws2)[t * 2 + 1] = make_float4(w[4], w[5], w[6], w[7]);
        __syncthreads();                                   // ws visible

        const float* xg = x + ((size_t)b * N_SZ + jc * JCHUNK) * DIN + t;
#pragma unroll 4
        for (int jj = 0; jj < JCHUNK; ++jj) {
            const ulonglong2 wA = ((const ulonglong2*)ws2)[jj * 2];
            const ulonglong2 wB = ((const ulonglong2*)ws2)[jj * 2 + 1];
            const u64 xv2 = pk2(xg[(size_t)jj * DIN]);
            acc[0] = fma2(wA.x, xv2, acc[0]);
            acc[1] = fma2(wA.y, xv2, acc[1]);
            acc[2] = fma2(wB.x, xv2, acc[2]);
            acc[3] = fma2(wB.y, xv2, acc[3]);
        }
        __syncthreads();                                   // agg done before restage
    }

#pragma unroll
    for (int off = 16; off > 0; off >>= 1)
#pragma unroll
        for (int r = 0; r < ITILE; ++r)
            rs[r] += __shfl_xor_sync(0xFFFFFFFFu, rs[r], off);
    const int warp = t >> 5, lane = t & 31;
    if (lane == 0)
#pragma unroll
        for (int r = 0; r < ITILE; ++r) redm[r][warp] = rs[r];

    float* ap = g_acc + (size_t)bi * ITILE * DIN + t;
#pragma unroll
    for (int p = 0; p < 4; ++p) {
        float lo, hi; upk(acc[p], lo, hi);
        ap[(2 * p) * DIN]     = lo;
        ap[(2 * p + 1) * DIN] = hi;
    }
    __syncthreads();
    if (t < ITILE)
        g_rs[bi * ITILE + t] = redm[t][0] + redm[t][1] + redm[t][2] + redm[t][3];
}

// ---------------------------------------------------------------------------
// Kernel 3: combine 4 partials + linear + lrelu. 256 threads, 2 outputs each.
// ---------------------------------------------------------------------------
__global__ void __launch_bounds__(256) gat_epilogue_kernel(
    const float* __restrict__ lin_w,   // [DOUT,DIN]
    float* __restrict__ out)           // [B,N,DOUT]
{
    __shared__ float outv[ITILE][DIN];
    __shared__ float red[ITILE];

    const int t    = threadIdx.x;
    const int tile = blockIdx.x;
    const int b    = tile >> 7;
    const int i0   = (tile & 127) * ITILE;

    const float* base = g_acc + (size_t)tile * SPLIT * ITILE * DIN;
    for (int l = t; l < ITILE * DIN; l += 256) {
        float s = base[l];
#pragma unroll
        for (int p = 1; p < SPLIT; ++p) s += base[p * ITILE * DIN + l];
        ((float*)outv)[l] = s;
    }
    if (t < ITILE) {
        float s = 0.f;
#pragma unroll
        for (int p = 0; p < SPLIT; ++p) s += g_rs[(tile * SPLIT + p) * ITILE + t];
        red[t] = s;
    }
    __syncthreads();

    const int k  = t & 63;
    const int rg = t >> 6;
    const float* lw = lin_w + k * DIN;
    float y0 = 0.f, y1 = 0.f;
#pragma unroll 8
    for (int d = 0; d < DIN; d += 4) {
        const float4 l4 = *(const float4*)&lw[d];
        const float4 oa = *(const float4*)&outv[rg][d];
        const float4 ob = *(const float4*)&outv[rg + 4][d];
        y0 += oa.x * l4.x + oa.y * l4.y + oa.z * l4.z + oa.w * l4.w;
        y1 += ob.x * l4.x + ob.y * l4.y + ob.z * l4.z + ob.w * l4.w;
    }
    const float inv0 = 1.0f / red[rg];
    const float inv1 = 1.0f / red[rg + 4];
    out[((size_t)b * N_SZ + i0 + rg)     * DOUT + k] = lrelu(y0) * inv0;
    out[((size_t)b * N_SZ + i0 + rg + 4) * DOUT + k] = lrelu(y1) * inv1;
}

// ---------------------------------------------------------------------------
extern "C" void kernel_launch(void* const* d_in, const int* in_sizes, int n_in,
                              void* d_out, int out_size)
{
    const float* x     = (const float*)d_in[0];
    const float* A_shp = (const float*)d_in[1];
    const float* w1    = (const float*)d_in[2];
    const float* w2    = (const float*)d_in[3];
    const float* a     = (const float*)d_in[4];
    const float* lin_w = (const float*)d_in[5];
    float* out = (float*)d_out;

    proj_kernel<<<B_SZ * N_SZ / PROWS, 256>>>(x, w1, w2, a);
    gat_score_agg_kernel<<<SPLIT * NTILES, 128>>>(x, A_shp, a);
    gat_epilogue_kernel<<<NTILES, 256>>>(lin_w, out);
}

// round 13
// speedup vs baseline: 1.5943x; 1.0025x over previous
#include <cuda_runtime.h>

#define B_SZ   4
#define N_SZ   1024
#define DIN    128
#define DOUT   64
#define ITILE  8
#define JCHUNK 128
#define PAD    129
#define NTILES (B_SZ * N_SZ / ITILE)     // 512 i-tiles
#define SPLIT  4
#define CHUNKS_PER 2
#define PROWS  8                         // proj rows per block (grid = 512)

__device__ float g_x1[B_SZ * N_SZ * DOUT];
__device__ float g_x2[B_SZ * N_SZ * DOUT];
__device__ float g_c1[B_SZ * N_SZ];
__device__ float g_c2[B_SZ * N_SZ];
__device__ float g_acc[SPLIT * NTILES * ITILE * DIN];   // 8 MB
__device__ float g_rs [SPLIT * NTILES * ITILE];

__device__ __forceinline__ float lrelu(float v) { return fmaxf(v, 0.01f * v); }

typedef unsigned long long u64;

__device__ __forceinline__ u64 pk2(float v) {
    u64 r; unsigned u = __float_as_uint(v);
    asm("mov.b64 %0, {%1, %1};" : "=l"(r) : "r"(u)); return r;
}
__device__ __forceinline__ u64 add2(u64 a, u64 b) {
    u64 r; asm("add.rn.f32x2 %0, %1, %2;" : "=l"(r) : "l"(a), "l"(b)); return r;
}
__device__ __forceinline__ u64 fma2(u64 a, u64 b, u64 c) {
    u64 r; asm("fma.rn.f32x2 %0, %1, %2, %3;" : "=l"(r) : "l"(a), "l"(b), "l"(c)); return r;
}
__device__ __forceinline__ void upk(u64 v, float& lo, float& hi) {
    unsigned a, b; asm("mov.b64 {%0, %1}, %2;" : "=r"(a), "=r"(b) : "l"(v));
    lo = __uint_as_float(a); hi = __uint_as_float(b);
}
#define ABS2 0x7FFFFFFF7FFFFFFFULL

// ---------------------------------------------------------------------------
// Kernel 1: x1 = x@w1, x2 = x@w2, c1 = x1.a, c2 = x2.a
// 8 rows/block, 512 blocks, 256 threads: thread = (col k, row-pair rg).
// ---------------------------------------------------------------------------
__global__ void __launch_bounds__(256) proj_kernel(
    const float* __restrict__ x,
    const float* __restrict__ w1,
    const float* __restrict__ w2,
    const float* __restrict__ a)
{
    __shared__ float xs[PROWS][DIN];            // 4 KB
    __shared__ float cred[2][4][2][2];          // [mat][rg][warp-half][q]

    const int t    = threadIdx.x;
    const int k    = t & 63;                    // output col
    const int rg   = t >> 6;                    // row pair 0..3
    const int base = blockIdx.x * PROWS;

    // stage 8 x-rows: 256 float4, one per thread
    ((float4*)xs)[t] = ((const float4*)(x + (size_t)base * DIN))[t];
    __syncthreads();

    float a10 = 0.f, a11 = 0.f, a20 = 0.f, a21 = 0.f;
#pragma unroll 16
    for (int d = 0; d < DIN; ++d) {
        const float wv1 = w1[d * DOUT + k];     // coalesced, L2-resident
        const float wv2 = w2[d * DOUT + k];
        const float x0  = xs[rg * 2][d];        // warp-broadcast LDS
        const float x1v = xs[rg * 2 + 1][d];
        a10 += x0  * wv1;  a11 += x1v * wv1;
        a20 += x0  * wv2;  a21 += x1v * wv2;
    }

    const int row0 = base + rg * 2;
    g_x1[(size_t)row0 * DOUT + k]       = a10;
    g_x1[(size_t)(row0 + 1) * DOUT + k] = a11;
    g_x2[(size_t)row0 * DOUT + k]       = a20;
    g_x2[(size_t)(row0 + 1) * DOUT + k] = a21;

    // c1/c2 reduction over k (64 cols = 2 warps per rg)
    const float av = a[k];
    float p10 = a10 * av, p11 = a11 * av, p20 = a20 * av, p21 = a21 * av;
#pragma unroll
    for (int off = 16; off > 0; off >>= 1) {
        p10 += __shfl_xor_sync(0xFFFFFFFFu, p10, off);
        p11 += __shfl_xor_sync(0xFFFFFFFFu, p11, off);
        p20 += __shfl_xor_sync(0xFFFFFFFFu, p20, off);
        p21 += __shfl_xor_sync(0xFFFFFFFFu, p21, off);
    }
    const int half = (t >> 5) & 1;
    if ((t & 31) == 0) {
        cred[0][rg][half][0] = p10;  cred[0][rg][half][1] = p11;
        cred[1][rg][half][0] = p20;  cred[1][rg][half][1] = p21;
    }
    __syncthreads();
    if (t < PROWS) {
        const int g = t >> 1, q = t & 1;
        g_c1[base + t] = cred[0][g][0][q] + cred[0][g][1][q];
        g_c2[base + t] = cred[1][g][0][q] + cred[1][g][1][q];
    }
}

// ---------------------------------------------------------------------------
// Kernel 2: score + exp/mask + partial aggregation over a quarter j-range.
// ---------------------------------------------------------------------------
__global__ void __launch_bounds__(128, 6) gat_score_agg_kernel(
    const float* __restrict__ x,       // [B,N,DIN]
    const float* __restrict__ mask,    // [B,N,N]
    const float* __restrict__ a)       // [DOUT]
{
    __shared__ __align__(16) float pool[DOUT * PAD];   // x2s [d][j]; ws aliased
    __shared__ __align__(16) float x1f[DOUT * ITILE];  // [d][r]
    __shared__ __align__(16) u64   a2s[DOUT];
    __shared__ float c1s[ITILE];
    __shared__ float redm[ITILE][4];

    u64* const ws2 = (u64*)pool;

    const int t    = threadIdx.x;
    const int bi   = blockIdx.x;
    const int tile = bi >> 2;
    const int part = bi & 3;
    const int b    = tile >> 7;
    const int i0   = (tile & 127) * ITILE;

    for (int l = t; l < ITILE * DOUT; l += 128) {
        const int r = l >> 6, d = l & 63;
        x1f[d * ITILE + r] = g_x1[(b * N_SZ + i0 + r) * DOUT + d];
    }
    if (t < DOUT) a2s[t] = pk2(a[t]);
    if (t < ITILE) c1s[t] = 0.505f * g_c1[b * N_SZ + i0 + t];

    u64 acc[4]; float rs[ITILE];
#pragma unroll
    for (int p = 0; p < 4; ++p) acc[p] = 0ULL;
#pragma unroll
    for (int r = 0; r < ITILE; ++r) rs[r] = 0.f;

    for (int c = 0; c < CHUNKS_PER; ++c) {
        const int jc = part * CHUNKS_PER + c;

        const float4* x2g4 = (const float4*)(g_x2 + (b * N_SZ + jc * JCHUNK) * DOUT);
        for (int l = t; l < JCHUNK * DOUT / 4; l += 128) {
            const float4 v = x2g4[l];
            const int j = l >> 4;
            const int d = (l & 15) * 4;
            pool[(d + 0) * PAD + j] = v.x;
            pool[(d + 1) * PAD + j] = v.y;
            pool[(d + 2) * PAD + j] = v.z;
            pool[(d + 3) * PAD + j] = v.w;
        }
        __syncthreads();                                   // x2s staged

        u64 T[4];
#pragma unroll
        for (int p = 0; p < 4; ++p) T[p] = 0ULL;

#pragma unroll 16
        for (int d = 0; d < DOUT; ++d) {
            const u64 xv2 = pk2(pool[d * PAD + t]);
            const u64 ad2 = a2s[d];
            const ulonglong2 xa = ((const ulonglong2*)x1f)[d * 2];
            const ulonglong2 xb = ((const ulonglong2*)x1f)[d * 2 + 1];
            T[0] = fma2(add2(xa.x, xv2) & ABS2, ad2, T[0]);
            T[1] = fma2(add2(xa.y, xv2) & ABS2, ad2, T[1]);
            T[2] = fma2(add2(xb.x, xv2) & ABS2, ad2, T[2]);
            T[3] = fma2(add2(xb.y, xv2) & ABS2, ad2, T[3]);
        }
        __syncthreads();                                   // x2s reads done (ws alias)

        const int j = jc * JCHUNK + t;
        const float c2j = 0.505f * g_c2[b * N_SZ + j];
        const float* mrow = mask + ((size_t)b * N_SZ + i0) * N_SZ + j;
        float w[ITILE];
#pragma unroll
        for (int p = 0; p < 4; ++p) {
            float t0, t1; upk(T[p], t0, t1);
            const float S0 = fmaf(0.495f, t0, c1s[2 * p]     + c2j);
            const float S1 = fmaf(0.495f, t1, c1s[2 * p + 1] + c2j);
            const float th0 = 1.0f - __fdividef(2.0f, __expf(S0 * 0.25f) + 1.0f);
            const float th1 = 1.0f - __fdividef(2.0f, __expf(S1 * 0.25f) + 1.0f);
            w[2 * p]     = __expf(8.0f * th0) * mrow[(size_t)(2 * p)     * N_SZ];
            w[2 * p + 1] = __expf(8.0f * th1) * mrow[(size_t)(2 * p + 1) * N_SZ];
            rs[2 * p]     += w[2 * p];
            rs[2 * p + 1] += w[2 * p + 1];
        }
        ((float4*)ws2)[t * 2]     = make_float4(w[0], w[1], w[2], w[3]);
        ((float4*)ws2)[t * 2 + 1] = make_float4(w[4], w[5], w[6], w[7]);
        __syncthreads();                                   // ws visible

        const float* xg = x + ((size_t)b * N_SZ + jc * JCHUNK) * DIN + t;
#pragma unroll 4
        for (int jj = 0; jj < JCHUNK; ++jj) {
            const ulonglong2 wA = ((const ulonglong2*)ws2)[jj * 2];
            const ulonglong2 wB = ((const ulonglong2*)ws2)[jj * 2 + 1];
            const u64 xv2 = pk2(xg[(size_t)jj * DIN]);
            acc[0] = fma2(wA.x, xv2, acc[0]);
            acc[1] = fma2(wA.y, xv2, acc[1]);
            acc[2] = fma2(wB.x, xv2, acc[2]);
            acc[3] = fma2(wB.y, xv2, acc[3]);
        }
        __syncthreads();                                   // agg done before restage
    }

#pragma unroll
    for (int off = 16; off > 0; off >>= 1)
#pragma unroll
        for (int r = 0; r < ITILE; ++r)
            rs[r] += __shfl_xor_sync(0xFFFFFFFFu, rs[r], off);
    const int warp = t >> 5, lane = t & 31;
    if (lane == 0)
#pragma unroll
        for (int r = 0; r < ITILE; ++r) redm[r][warp] = rs[r];

    float* ap = g_acc + (size_t)bi * ITILE * DIN + t;
#pragma unroll
    for (int p = 0; p < 4; ++p) {
        float lo, hi; upk(acc[p], lo, hi);
        ap[(2 * p) * DIN]     = lo;
        ap[(2 * p + 1) * DIN] = hi;
    }
    __syncthreads();
    if (t < ITILE)
        g_rs[bi * ITILE + t] = redm[t][0] + redm[t][1] + redm[t][2] + redm[t][3];
}

// ---------------------------------------------------------------------------
// Kernel 3: combine 4 partials + linear + lrelu. 256 threads, 2 outputs each.
// ---------------------------------------------------------------------------
__global__ void __launch_bounds__(256) gat_epilogue_kernel(
    const float* __restrict__ lin_w,   // [DOUT,DIN]
    float* __restrict__ out)           // [B,N,DOUT]
{
    __shared__ float outv[ITILE][DIN];
    __shared__ float red[ITILE];

    const int t    = threadIdx.x;
    const int tile = blockIdx.x;
    const int b    = tile >> 7;
    const int i0   = (tile & 127) * ITILE;

    const float* base = g_acc + (size_t)tile * SPLIT * ITILE * DIN;
    for (int l = t; l < ITILE * DIN; l += 256) {
        float s = base[l];
#pragma unroll
        for (int p = 1; p < SPLIT; ++p) s += base[p * ITILE * DIN + l];
        ((float*)outv)[l] = s;
    }
    if (t < ITILE) {
        float s = 0.f;
#pragma unroll
        for (int p = 0; p < SPLIT; ++p) s += g_rs[(tile * SPLIT + p) * ITILE + t];
        red[t] = s;
    }
    __syncthreads();

    const int k  = t & 63;
    const int rg = t >> 6;
    const float* lw = lin_w + k * DIN;
    float y0 = 0.f, y1 = 0.f;
#pragma unroll 8
    for (int d = 0; d < DIN; d += 4) {
        const float4 l4 = *(const float4*)&lw[d];
        const float4 oa = *(const float4*)&outv[rg][d];
        const float4 ob = *(const float4*)&outv[rg + 4][d];
        y0 += oa.x * l4.x + oa.y * l4.y + oa.z * l4.z + oa.w * l4.w;
        y1 += ob.x * l4.x + ob.y * l4.y + ob.z * l4.z + ob.w * l4.w;
    }
    const float inv0 = 1.0f / red[rg];
    const float inv1 = 1.0f / red[rg + 4];
    out[((size_t)b * N_SZ + i0 + rg)     * DOUT + k] = lrelu(y0) * inv0;
    out[((size_t)b * N_SZ + i0 + rg + 4) * DOUT + k] = lrelu(y1) * inv1;
}

// ---------------------------------------------------------------------------
extern "C" void kernel_launch(void* const* d_in, const int* in_sizes, int n_in,
                              void* d_out, int out_size)
{
    const float* x     = (const float*)d_in[0];
    const float* A_shp = (const float*)d_in[1];
    const float* w1    = (const float*)d_in[2];
    const float* w2    = (const float*)d_in[3];
    const float* a     = (const float*)d_in[4];
    const float* lin_w = (const float*)d_in[5];
    float* out = (float*)d_out;

    proj_kernel<<<B_SZ * N_SZ / PROWS, 256>>>(x, w1, w2, a);
    gat_score_agg_kernel<<<SPLIT * NTILES, 128>>>(x, A_shp, a);
    gat_epilogue_kernel<<<NTILES, 256>>>(lin_w, out);
}